// round 2
// baseline (speedup 1.0000x reference)
#include <cuda_runtime.h>

// Problem constants (fixed by the reference).
#define BATCH   32
#define NIN     1024
#define NOUT    1024
#define DECAYF  0.8f          // 1 - 1/TAU, TAU = 5
#define CHUNK   32            // i-rows per block
#define NCHUNK  (NIN / CHUNK) // 32
#define TPB     256           // 256 threads * float4 = 1024 = NOUT

__global__ void zero_out_kernel(float* __restrict__ out) {
    int i = blockIdx.x * blockDim.x + threadIdx.x;
    if (i < BATCH * NOUT) out[i] = 0.0f;
}

__global__ __launch_bounds__(TPB) void synapse_kernel(
    const float* __restrict__ spikes,   // [B, NIN]
    const float* __restrict__ mem,      // [B, NOUT]
    const float* __restrict__ rev,      // [B, NIN]
    const float* __restrict__ syn,      // [B, NIN, NOUT]
    const float* __restrict__ weights,  // [NIN, NOUT]
    float* __restrict__ out)            // [B, NOUT], pre-zeroed
{
    __shared__ float s_rev[CHUNK];
    __shared__ float s_spk[CHUNK];

    const int b  = blockIdx.y;
    const int i0 = blockIdx.z * CHUNK;
    const int o4 = threadIdx.x * 4;      // first of this thread's 4 outputs

    // Stage the per-i broadcast operands.
    if (threadIdx.x < CHUNK) {
        s_rev[threadIdx.x] = rev[b * NIN + i0 + threadIdx.x];
        s_spk[threadIdx.x] = spikes[b * NIN + i0 + threadIdx.x];
    }
    __syncthreads();

    const float4 m4 = *reinterpret_cast<const float4*>(mem + b * NOUT + o4);

    const float4* __restrict__ synp =
        reinterpret_cast<const float4*>(syn + ((size_t)b * NIN + i0) * NOUT + o4);
    const float4* __restrict__ wp =
        reinterpret_cast<const float4*>(weights + (size_t)i0 * NOUT + o4);

    float acc0 = 0.f, acc1 = 0.f, acc2 = 0.f, acc3 = 0.f;

    #pragma unroll 8
    for (int i = 0; i < CHUNK; ++i) {
        const float4 s = synp[i * (NOUT / 4)];   // 128 MB stream — the roofline
        const float4 w = wp[i * (NOUT / 4)];     // L2-resident (4 MB total)
        const float  r  = s_rev[i];
        const float  sp = s_spk[i];

        // v = syn*decay + spike ; acc += (v*w) * (rev - mem)
        float v0 = fmaf(s.x, DECAYF, sp);
        float v1 = fmaf(s.y, DECAYF, sp);
        float v2 = fmaf(s.z, DECAYF, sp);
        float v3 = fmaf(s.w, DECAYF, sp);
        acc0 = fmaf(v0 * w.x, r - m4.x, acc0);
        acc1 = fmaf(v1 * w.y, r - m4.y, acc1);
        acc2 = fmaf(v2 * w.z, r - m4.z, acc2);
        acc3 = fmaf(v3 * w.w, r - m4.w, acc3);
    }

    float* op = out + b * NOUT + o4;
    atomicAdd(op + 0, acc0);
    atomicAdd(op + 1, acc1);
    atomicAdd(op + 2, acc2);
    atomicAdd(op + 3, acc3);
}

extern "C" void kernel_launch(void* const* d_in, const int* in_sizes, int n_in,
                              void* d_out, int out_size) {
    // metadata order == setup_inputs dict order:
    const float* spikes  = (const float*)d_in[0];  // [32, 1024]
    const float* mem     = (const float*)d_in[1];  // [32, 1024]
    const float* rev     = (const float*)d_in[2];  // [32, 1024]
    const float* syn     = (const float*)d_in[3];  // [32, 1024, 1024]
    const float* weights = (const float*)d_in[4];  // [1024, 1024]
    float* out = (float*)d_out;

    zero_out_kernel<<<(BATCH * NOUT + TPB - 1) / TPB, TPB>>>(out);

    dim3 grid(1, BATCH, NCHUNK);   // 1 o-tile x 32 b x 32 i-chunks = 1024 blocks
    synapse_kernel<<<grid, TPB>>>(spikes, mem, rev, syn, weights, out);
}